// round 14
// baseline (speedup 1.0000x reference)
#include <cuda_runtime.h>
#include <cuda_bf16.h>

// LSEP loss, factorized:
//   S_b = (sum_{neg} e^{x}) * (sum_{pos} e^{-x});  loss = mean_b log1p(S_b)
// N = 512 rows, C = 512 cols.
//
// Single kernel node, 128 CTAs x 512 threads (4 rows per CTA); exactly one
// float4 + one int4 load per thread. Cross-CTA combine = ONE 64-bit integer
// atomicAdd per CTA into g_pack:
//   bits [52..62) : arrival count (each CTA adds 1<<52; target 127)
//   bits [0..52)  : fixed-point sum of log1p(S_row), scale 2^26
// Deterministic. Last CTA publishes out[0]; reset is a plain store.
// Replay-idempotent, no memset node, no fences.
//
// R14: warp reduction via REDUX.SYNC.ADD.u32 (__reduce_add_sync) on u16.16
// fixed-point partials — one HW op instead of a 5-level shuffle chain.
// Range proof: |pred| <= ~4.7 -> e^x <= ~110; per-thread partial <= 4*110*2^16
// ~= 2.9e7; warp sum <= 9.2e8 < 2^32. Quantization ~2^-17/term -> rel err of
// row sums ~1e-5, far inside the 1e-3 gate.

#define NROWS 512
#define NCOLS 512
#define ROWS_PER_CTA 4
#define NBLOCKS (NROWS / ROWS_PER_CTA)   // 128
#define NTHREADS (128 * ROWS_PER_CTA)    // 512

#define CNT_ONE  (1ULL << 52)
#define VAL_MASK (CNT_ONE - 1ULL)
#define FP_SCALE 67108864.0f             // 2^26 (CTA-level encode)
#define INV_SCALE_OVER_N (1.0f / (67108864.0f * 512.0f))

#define WARP_FX   65536.0f               // 2^16 (warp-level u16.16)
#define INV_WARP_FX (1.0f / 65536.0f)

__device__ unsigned long long g_pack;   // zero-initialized; reset each run

__global__ void __launch_bounds__(NTHREADS) lsep_kernel(
    const int* __restrict__ y_true,
    const float* __restrict__ y_pred,
    float* __restrict__ out)
{
    const int t       = threadIdx.x;
    const int row_loc = t >> 7;                 // 0..3 within CTA
    const int idx     = t & 127;                // float4 index within row
    const int row     = blockIdx.x * ROWS_PER_CTA + row_loc;

    const float4* __restrict__ pv = reinterpret_cast<const float4*>(y_pred + row * NCOLS);
    const int4*   __restrict__ tv = reinterpret_cast<const int4*>(y_true + row * NCOLS);

    float4 v = pv[idx];
    int4   l = tv[idx];

    float pos = 0.f, neg = 0.f;

    // Branchless: flip sign of v when label==1, exp once, route to pos/neg.
#define ACC(LBL, VAL) do {                                              \
        float x = __int_as_float(__float_as_int(VAL) ^ ((LBL) << 31));  \
        float e = __expf(x);                                            \
        float fl = (float)(LBL);                                        \
        pos = fmaf(fl, e, pos);                                         \
        neg = fmaf(1.0f - fl, e, neg);                                  \
    } while (0)

    ACC(l.x, v.x);
    ACC(l.y, v.y);
    ACC(l.z, v.z);
    ACC(l.w, v.w);
#undef ACC

    // Warp reduction: single REDUX.SYNC.ADD per accumulator on u16.16
    // fixed point (two independent ops, pipelined).
    unsigned int pos_fx = (unsigned int)fmaf(pos, WARP_FX, 0.5f);
    unsigned int neg_fx = (unsigned int)fmaf(neg, WARP_FX, 0.5f);
    unsigned int pos_w  = __reduce_add_sync(0xFFFFFFFFu, pos_fx);
    unsigned int neg_w  = __reduce_add_sync(0xFFFFFFFFu, neg_fx);

    __shared__ float s_pos[16];
    __shared__ float s_neg[16];
    const int wid  = t >> 5;    // warps 4r..4r+3 belong to row r
    const int lane = t & 31;
    if (lane == 0) {
        s_pos[wid] = (float)pos_w * INV_WARP_FX;
        s_neg[wid] = (float)neg_w * INV_WARP_FX;
    }
    __syncthreads();

    if (wid == 0) {
        // lanes 0..3 each finalize one row; other lanes contribute 0
        float contrib = 0.f;
        if (lane < ROWS_PER_CTA) {
            const int r4 = lane * 4;
            float p = s_pos[r4] + s_pos[r4 + 1] + s_pos[r4 + 2] + s_pos[r4 + 3];
            float n = s_neg[r4] + s_neg[r4 + 1] + s_neg[r4 + 2] + s_neg[r4 + 3];
            contrib = __logf(1.0f + p * n);
        }
        contrib += __shfl_xor_sync(0xFFFFFFFFu, contrib, 2);
        contrib += __shfl_xor_sync(0xFFFFFFFFu, contrib, 1);

        if (lane == 0) {
            // fixed-point encode in fp32 (quantization ~5e-7 absolute per row)
            unsigned long long fx = (unsigned long long)(contrib * FP_SCALE);
            unsigned long long prev = atomicAdd(&g_pack, CNT_ONE | fx);

            if ((prev >> 52) == (unsigned long long)(NBLOCKS - 1)) {
                unsigned long long total_fx = (prev & VAL_MASK) + fx;
                out[0] = (float)total_fx * INV_SCALE_OVER_N;
                // After count saturation no other CTA touches g_pack:
                // plain store reset is race-free.
                *(volatile unsigned long long*)&g_pack = 0ULL;
            }
        }
    }
}

extern "C" void kernel_launch(void* const* d_in, const int* in_sizes, int n_in,
                              void* d_out, int out_size)
{
    const int*   y_true = (const int*)d_in[0];
    const float* y_pred = (const float*)d_in[1];
    float* out = (float*)d_out;

    lsep_kernel<<<NBLOCKS, NTHREADS>>>(y_true, y_pred, out);
}

// round 17
// speedup vs baseline: 1.0337x; 1.0337x over previous
#include <cuda_runtime.h>
#include <cuda_bf16.h>

// LSEP loss, factorized:
//   S_b = (sum_{neg} e^{x}) * (sum_{pos} e^{-x});  loss = mean_b log1p(S_b)
// N = 512 rows, C = 512 cols.
//
// Single kernel node, 128 CTAs x 512 threads (4 rows per CTA); exactly one
// float4 + one int4 load per thread. R15: the four row-groups inside a CTA
// are fully DECOUPLED — each group of 4 warps syncs on its own named barrier
// (bar.sync id, 128) and publishes its row independently, so no row waits on
// a sibling row's load stragglers. 512 packed-u64 atomicAdds total (chain
// length proven perf-irrelevant):
//   bits [52..62) : arrival count (each row adds 1<<52; target 511)
//   bits [0..52)  : fixed-point sum of log1p(S_row), scale 2^26
// Deterministic (integer adds). Last arrival publishes out[0]; reset is a
// plain store. Replay-idempotent, no memset node, no fences.

#define NROWS 512
#define NCOLS 512
#define ROWS_PER_CTA 4
#define NBLOCKS (NROWS / ROWS_PER_CTA)   // 128
#define NTHREADS (128 * ROWS_PER_CTA)    // 512

#define CNT_ONE  (1ULL << 52)
#define VAL_MASK (CNT_ONE - 1ULL)
#define FP_SCALE 67108864.0f             // 2^26
#define INV_SCALE_OVER_N (1.0f / (67108864.0f * 512.0f))

__device__ unsigned long long g_pack;   // zero-initialized; reset each run

__global__ void __launch_bounds__(NTHREADS) lsep_kernel(
    const int* __restrict__ y_true,
    const float* __restrict__ y_pred,
    float* __restrict__ out)
{
    const int t       = threadIdx.x;
    const int row_loc = t >> 7;                 // 0..3 within CTA
    const int idx     = t & 127;                // float4 index within row
    const int row     = blockIdx.x * ROWS_PER_CTA + row_loc;

    const float4* __restrict__ pv = reinterpret_cast<const float4*>(y_pred + row * NCOLS);
    const int4*   __restrict__ tv = reinterpret_cast<const int4*>(y_true + row * NCOLS);

    float4 v = pv[idx];
    int4   l = tv[idx];

    float pos = 0.f, neg = 0.f;

    // Branchless: flip sign of v when label==1, exp once, route to pos/neg.
#define ACC(LBL, VAL) do {                                              \
        float x = __int_as_float(__float_as_int(VAL) ^ ((LBL) << 31));  \
        float e = __expf(x);                                            \
        float fl = (float)(LBL);                                        \
        pos = fmaf(fl, e, pos);                                         \
        neg = fmaf(1.0f - fl, e, neg);                                  \
    } while (0)

    ACC(l.x, v.x);
    ACC(l.y, v.y);
    ACC(l.z, v.z);
    ACC(l.w, v.w);
#undef ACC

    // warp reduction (two independent shuffle chains, pipelined)
    #pragma unroll
    for (int off = 16; off > 0; off >>= 1) {
        pos += __shfl_xor_sync(0xFFFFFFFFu, pos, off);
        neg += __shfl_xor_sync(0xFFFFFFFFu, neg, off);
    }

    __shared__ float s_pos[16];
    __shared__ float s_neg[16];
    const int wid  = t >> 5;                    // warps 4r..4r+3 = row r
    const int lane = t & 31;
    if (lane == 0) { s_pos[wid] = pos; s_neg[wid] = neg; }

    // Per-row-group barrier: only this row's 4 warps participate (ids 1..4).
    asm volatile("bar.sync %0, 128;" :: "r"(row_loc + 1) : "memory");

    // First warp of each group finalizes its own row — no cross-row wait.
    if ((wid & 3) == 0 && lane == 0) {
        const int r4 = row_loc * 4;
        float p = s_pos[r4] + s_pos[r4 + 1] + s_pos[r4 + 2] + s_pos[r4 + 3];
        float n = s_neg[r4] + s_neg[r4 + 1] + s_neg[r4 + 2] + s_neg[r4 + 3];
        float contrib = __logf(1.0f + p * n);

        // fixed-point encode in fp32 (quantization ~5e-7 absolute per row)
        unsigned long long fx = (unsigned long long)(contrib * FP_SCALE);
        unsigned long long prev = atomicAdd(&g_pack, CNT_ONE | fx);

        if ((prev >> 52) == (unsigned long long)(NROWS - 1)) {
            unsigned long long total_fx = (prev & VAL_MASK) + fx;
            out[0] = (float)total_fx * INV_SCALE_OVER_N;
            // After count saturation no other thread touches g_pack:
            // plain store reset is race-free.
            *(volatile unsigned long long*)&g_pack = 0ULL;
        }
    }
}

extern "C" void kernel_launch(void* const* d_in, const int* in_sizes, int n_in,
                              void* d_out, int out_size)
{
    const int*   y_true = (const int*)d_in[0];
    const float* y_pred = (const float*)d_in[1];
    float* out = (float*)d_out;

    lsep_kernel<<<NBLOCKS, NTHREADS>>>(y_true, y_pred, out);
}